// round 17
// baseline (speedup 1.0000x reference)
#include <cuda_runtime.h>
#include <cuda_bf16.h>
#include <cstdint>

#define Bn 16
#define Cn 32
#define Tn 2048
#define Kn 129
#define SR 384            // s-range per CTA (256 outputs + 128 halo)
#define NTH 512
#define ZP 36             // pitch%32==4: LDS.32 frag loads (4g+tig) conflict-free
#define WP 36
#define QT 132            // qsT pitch: stores banks 8tig+g, gather consecutive -> CF
#define CH 64             // s-chunk size
#define NCHUNK 6

// ---- smem byte offsets ----
#define OFF_ZH 0
#define SZ_Z   (SR * ZP * 4)            // 55296
#define OFF_ZL (OFF_ZH + SZ_Z)          // 55296
#define OFF_WH (OFF_ZL + SZ_Z)          // 110592
#define SZ_W   (128 * WP * 4)           // 18432
#define OFF_WL (OFF_WH + SZ_W)          // 129024
#define OFF_QS0 (OFF_WL + SZ_W)         // 147456
#define SZ_QS1 (CH * QT * 4)            // 33792
#define OFF_QS1 (OFF_QS0 + SZ_QS1)      // 181248
#define OFF_AF (OFF_QS1 + SZ_QS1)       // 215040
#define OFF_BS (OFF_AF + 256)
#define OFF_WT (OFF_BS + 256)
#define OFF_RED (OFF_WT + 256)          // 256 f32 half-sum exchange
#define SMEM_BYTES (OFF_RED + 1024)     // 216832

// split v0,v1 into bf16 hi + bf16 lo pairs, packed (low half = v0)
__device__ __forceinline__ void split2(float v0, float v1, uint32_t& h, uint32_t& l) {
    __nv_bfloat162 hh = __floats2bfloat162_rn(v0, v1);
    float r0 = v0 - __bfloat162float(hh.x);
    float r1 = v1 - __bfloat162float(hh.y);
    __nv_bfloat162 ll = __floats2bfloat162_rn(r0, r1);
    h = *(uint32_t*)&hh;
    l = *(uint32_t*)&ll;
}

// m16n8k16 bf16 mma, fp32 accum (base ISA on sm_103)
__device__ __forceinline__ void mma16816(float* c, const uint32_t* a, const uint32_t* b) {
    asm volatile(
        "mma.sync.aligned.m16n8k16.row.col.f32.bf16.bf16.f32 "
        "{%0,%1,%2,%3}, {%4,%5,%6,%7}, {%8,%9}, {%0,%1,%2,%3};"
        : "+f"(c[0]), "+f"(c[1]), "+f"(c[2]), "+f"(c[3])
        : "r"(a[0]), "r"(a[1]), "r"(a[2]), "r"(a[3]), "r"(b[0]), "r"(b[1]));
}

__global__ __launch_bounds__(NTH, 1)
void wavelet_mma_kernel(
    const float* __restrict__ coeffs,     // (B,2,F,7,5,T)
    const int*   __restrict__ rows,       // (C)
    const int*   __restrict__ cols,       // (C)
    const float* __restrict__ ri_scale,   // (F)
    const float* __restrict__ ri_shift,   // (F)
    const float* __restrict__ freq_gain,  // (F)
    const float* __restrict__ synth_w,    // (C*64, 1, 129)
    float*       __restrict__ out)        // (B,C,T)
{
    extern __shared__ char smem[];
    uint32_t* zh = (uint32_t*)(smem + OFF_ZH);
    uint32_t* zl = (uint32_t*)(smem + OFF_ZL);
    uint32_t* wh = (uint32_t*)(smem + OFF_WH);
    uint32_t* wl = (uint32_t*)(smem + OFF_WL);
    float*    af = (float*)(smem + OFF_AF);
    float*    bs = (float*)(smem + OFF_BS);
    float*    wt = (float*)(smem + OFF_WT);
    float*    red = (float*)(smem + OFF_RED);

    const int tid  = threadIdx.x;
    const int wid  = tid >> 5;
    const int lane = tid & 31;
    const int g    = lane >> 2;     // fragment row (0..7)
    const int tig  = lane & 3;      // thread-in-group

    const int bid   = blockIdx.x;
    const int chunk = bid & 7;
    const int c     = (bid >> 3) & 31;
    const int b     = bid >> 8;
    const int t0    = chunk << 8;

    const int rr = rows[c];
    const int cc = cols[c];

    // ---- per-channel constants + tail weights ----
    if (tid < 64) {
        const int f = tid & 31;
        const float gg = freq_gain[f];
        af[tid] = gg / (ri_scale[f] + 1e-12f);
        bs[tid] = ri_shift[f] * gg;
        wt[tid] = synth_w[(size_t)(c * 64 + tid) * Kn + 128];
    }
    __syncthreads();

    // ---- W fill: plain layout, word w <-> channel pair (2w, 2w+1) ----
    {
        const int j   = tid >> 2;
        const int grp = tid & 3;
        const float* wrow = synth_w + (size_t)(c * 64) * Kn + j;
#pragma unroll
        for (int q = 0; q < 8; ++q) {
            const int w  = grp * 8 + q;
            const int ch = 2 * w;
            const float w0 = wrow[(size_t)ch * Kn];
            const float w1 = wrow[(size_t)(ch + 1) * Kn];
            uint32_t h, l;
            split2(w0, w1, h, l);
            wh[j * WP + w] = h;
            wl[j * WP + w] = l;
        }
    }

    // ---- z fill: one row per thread; plain layout; STS.128 (conflict-free) ----
    const float* cb = coeffs + (size_t)(b * 64) * 71680 + (size_t)(rr * 5 + cc) * Tn;
    if (tid < SR) {
        const int s = tid;
        const int t = t0 - 64 + s;
        const bool valid = (unsigned)t < (unsigned)Tn;
#pragma unroll
        for (int w4 = 0; w4 < 8; ++w4) {          // 8 uint4 per row (32 words)
            uint32_t hw[4], lw[4];
#pragma unroll
            for (int e = 0; e < 4; ++e) {
                const int w  = w4 * 4 + e;
                const int ch = 2 * w;
                float v0 = valid ? fmaf(cb[(size_t)ch * 71680 + t], af[ch], -bs[ch]) : 0.f;
                float v1 = valid ? fmaf(cb[(size_t)(ch + 1) * 71680 + t], af[ch + 1], -bs[ch + 1]) : 0.f;
                split2(v0, v1, hw[e], lw[e]);
            }
            *(uint4*)&zh[s * ZP + w4 * 4] = make_uint4(hw[0], hw[1], hw[2], hw[3]);
            *(uint4*)&zl[s * ZP + w4 * 4] = make_uint4(lw[0], lw[1], lw[2], lw[3]);
        }
    }
    __syncthreads();

    // ---- merged GEMM + gather over 6 s-chunks of 64, double-buffered qsT ----
    // 16 warps = 4 j-groups (2 m16 tiles) x 4 n-groups (2 n8 tiles)
    const int jbase = (wid >> 2) * 32;
    const int nbase = (wid & 3) * 16;
    const int u  = tid & 255;          // output index (2 threads per output)
    const int hf = tid >> 8;           // gather half (32 s-cols each)
    float osum = 0.f;

#pragma unroll 1
    for (int m = 0; m < NCHUNK; ++m) {
        const int c0g = m * CH;
        float* qsw = (float*)(smem + ((m & 1) ? OFF_QS1 : OFF_QS0));

        float acc[2][2][4];
#pragma unroll
        for (int jt = 0; jt < 2; ++jt)
#pragma unroll
            for (int nt = 0; nt < 2; ++nt)
#pragma unroll
                for (int q = 0; q < 4; ++q) acc[jt][nt][q] = 0.f;

#pragma unroll
        for (int ks = 0; ks < 4; ++ks) {
            const int kw = ks * 8 + tig;          // LDS.32 mapping, CF
            uint32_t ah[2][4], al[2][4];
#pragma unroll
            for (int jt = 0; jt < 2; ++jt) {
                const int r = jbase + jt * 16 + g;
                ah[jt][0] = wh[r * WP + kw];
                ah[jt][1] = wh[(r + 8) * WP + kw];
                ah[jt][2] = wh[r * WP + kw + 4];
                ah[jt][3] = wh[(r + 8) * WP + kw + 4];
                al[jt][0] = wl[r * WP + kw];
                al[jt][1] = wl[(r + 8) * WP + kw];
                al[jt][2] = wl[r * WP + kw + 4];
                al[jt][3] = wl[(r + 8) * WP + kw + 4];
            }
            uint32_t bh[2][2], bl[2][2];
#pragma unroll
            for (int nt = 0; nt < 2; ++nt) {
                const int srow = c0g + nbase + nt * 8 + g;
                bh[nt][0] = zh[srow * ZP + kw];
                bh[nt][1] = zh[srow * ZP + kw + 4];
                bl[nt][0] = zl[srow * ZP + kw];
                bl[nt][1] = zl[srow * ZP + kw + 4];
            }
#pragma unroll
            for (int jt = 0; jt < 2; ++jt)
#pragma unroll
                for (int nt = 0; nt < 2; ++nt) {
                    mma16816(acc[jt][nt], ah[jt], bh[nt]);
                    mma16816(acc[jt][nt], ah[jt], bl[nt]);
                    mma16816(acc[jt][nt], al[jt], bh[nt]);
                }
        }

        // store transposed: qsT[sl][j]  (STS.32, banks 8tig+g: conflict-free)
#pragma unroll
        for (int jt = 0; jt < 2; ++jt)
#pragma unroll
            for (int nt = 0; nt < 2; ++nt) {
                const int r   = jbase + jt * 16 + g;
                const int col = nbase + nt * 8 + 2 * tig;
                qsw[col * QT + r]           = acc[jt][nt][0];
                qsw[(col + 1) * QT + r]     = acc[jt][nt][1];
                qsw[col * QT + r + 8]       = acc[jt][nt][2];
                qsw[(col + 1) * QT + r + 8] = acc[jt][nt][3];
            }

        // gather previous chunk (overlaps with this chunk's MMA stream)
        if (m > 0) {
            const int cp = (m - 1) * CH;
            const float* qsr = (const float*)(smem + (((m - 1) & 1) ? OFF_QS1 : OFF_QS0));
            const int slb = hf * 32;
            const int jb  = u + 128 - cp - slb;
            float ga0 = 0.f, ga1 = 0.f, ga2 = 0.f, ga3 = 0.f;
#pragma unroll
            for (int k = 0; k < 32; k += 4) {
                const int j0 = jb - k;
                const int sl = slb + k;
                if ((unsigned)j0 < 128u)       ga0 += qsr[sl * QT + j0];
                if ((unsigned)(j0 - 1) < 128u) ga1 += qsr[(sl + 1) * QT + j0 - 1];
                if ((unsigned)(j0 - 2) < 128u) ga2 += qsr[(sl + 2) * QT + j0 - 2];
                if ((unsigned)(j0 - 3) < 128u) ga3 += qsr[(sl + 3) * QT + j0 - 3];
            }
            osum += (ga0 + ga1) + (ga2 + ga3);
        }
        __syncthreads();
    }

    // ---- gather last chunk ----
    {
        const int cp = (NCHUNK - 1) * CH;
        const float* qsr = (const float*)(smem + (((NCHUNK - 1) & 1) ? OFF_QS1 : OFF_QS0));
        const int slb = hf * 32;
        const int jb  = u + 128 - cp - slb;
        float ga0 = 0.f, ga1 = 0.f, ga2 = 0.f, ga3 = 0.f;
#pragma unroll
        for (int k = 0; k < 32; k += 4) {
            const int j0 = jb - k;
            const int sl = slb + k;
            if ((unsigned)j0 < 128u)       ga0 += qsr[sl * QT + j0];
            if ((unsigned)(j0 - 1) < 128u) ga1 += qsr[(sl + 1) * QT + j0 - 1];
            if ((unsigned)(j0 - 2) < 128u) ga2 += qsr[(sl + 2) * QT + j0 - 2];
            if ((unsigned)(j0 - 3) < 128u) ga3 += qsr[(sl + 3) * QT + j0 - 3];
        }
        osum += (ga0 + ga1) + (ga2 + ga3);
    }

    // ---- combine thread-halves, add tail (j=128, s=u), write out ----
    if (hf == 1) red[u] = osum;
    __syncthreads();
    if (hf == 0) {
        float tot = osum + red[u];
        const int s = u;                // local s = u for the j=128 tap
        float tail = 0.f;
#pragma unroll
        for (int w4 = 0; w4 < 8; ++w4) {
            const uint4 h4 = *(const uint4*)&zh[s * ZP + w4 * 4];
            const uint4 l4 = *(const uint4*)&zl[s * ZP + w4 * 4];
            const uint32_t hws[4] = {h4.x, h4.y, h4.z, h4.w};
            const uint32_t lws[4] = {l4.x, l4.y, l4.z, l4.w};
#pragma unroll
            for (int e = 0; e < 4; ++e) {
                const int ch = 2 * (w4 * 4 + e);
                const __nv_bfloat162 h2 = *(const __nv_bfloat162*)&hws[e];
                const __nv_bfloat162 l2 = *(const __nv_bfloat162*)&lws[e];
                tail += (__bfloat162float(h2.x) + __bfloat162float(l2.x)) * wt[ch];
                tail += (__bfloat162float(h2.y) + __bfloat162float(l2.y)) * wt[ch + 1];
            }
        }
        out[(size_t)(b * Cn + c) * Tn + t0 + u] = tot + tail;
    }
}

extern "C" void kernel_launch(void* const* d_in, const int* in_sizes, int n_in,
                              void* d_out, int out_size) {
    (void)in_sizes; (void)n_in; (void)out_size;
    const float* coeffs    = (const float*)d_in[0];
    const int*   rows      = (const int*)  d_in[1];
    const int*   cols      = (const int*)  d_in[2];
    const float* ri_scale  = (const float*)d_in[3];
    const float* ri_shift  = (const float*)d_in[4];
    const float* freq_gain = (const float*)d_in[5];
    const float* synth_w   = (const float*)d_in[6];
    float* out = (float*)d_out;

    cudaFuncSetAttribute(wavelet_mma_kernel,
                         cudaFuncAttributeMaxDynamicSharedMemorySize, SMEM_BYTES);
    wavelet_mma_kernel<<<Bn * Cn * 8, NTH, SMEM_BYTES>>>(
        coeffs, rows, cols, ri_scale, ri_shift, freq_gain, synth_w, out);
}